// round 6
// baseline (speedup 1.0000x reference)
#include <cuda_runtime.h>
#include <cstdint>

#define B_ROWS 8192
#define K_DIM  784
#define N_DIM  800
#define NSTEPS 25
#define NTILES (K_DIM / 8)   // 98

// ---------------- device scratch (static globals: no runtime allocation) ----
__device__ float g_sp  [B_ROWS * K_DIM];   // Poisson spike matrix {0, 0.5, 1}
__device__ float g_mem1[B_ROWS * N_DIM];   // membrane potential
__device__ float g_S   [B_ROWS * N_DIM];   // spike counts
__device__ uint2 g_keys[NSTEPS];           // per-step threefry keys

// ---------------- threefry2x32 (matches JAX, 20 rounds) --------------------
__device__ __forceinline__ void threefry2x32(uint32_t k0, uint32_t k1,
                                             uint32_t x0, uint32_t x1,
                                             uint32_t &o0, uint32_t &o1) {
    uint32_t ks0 = k0, ks1 = k1, ks2 = 0x1BD11BDAu ^ k0 ^ k1;
    x0 += ks0; x1 += ks1;
#define TF_R(r) { x0 += x1; x1 = __funnelshift_l(x1, x1, (r)); x1 ^= x0; }
    TF_R(13) TF_R(15) TF_R(26) TF_R(6)
    x0 += ks1; x1 += ks2 + 1u;
    TF_R(17) TF_R(29) TF_R(16) TF_R(24)
    x0 += ks2; x1 += ks0 + 2u;
    TF_R(13) TF_R(15) TF_R(26) TF_R(6)
    x0 += ks0; x1 += ks1 + 3u;
    TF_R(17) TF_R(29) TF_R(16) TF_R(24)
    x0 += ks1; x1 += ks2 + 4u;
    TF_R(13) TF_R(15) TF_R(26) TF_R(6)
    x0 += ks2; x1 += ks0 + 5u;
#undef TF_R
    o0 = x0; o1 = x1;
}

// ---------------- init: per-step keys ---------------------------------------
__global__ void k_init() {
    int t = threadIdx.x;
    if (t < NSTEPS) {
        uint32_t o0, o1;
        threefry2x32(0u, 42u, 0u, (uint32_t)t, o0, o1);
        g_keys[t] = make_uint2(o0, o1);
    }
}

// ---------------- zero state ------------------------------------------------
__global__ void k_zero() {
    int i = blockIdx.x * blockDim.x + threadIdx.x;
    if (i < B_ROWS * N_DIM) { g_mem1[i] = 0.0f; g_S[i] = 0.0f; }
}

// ---------------- per-step spike (Poisson) generation -----------------------
__global__ void k_spike(const float* __restrict__ inp, int t) {
    int i = blockIdx.x * blockDim.x + threadIdx.x;
    if (i >= B_ROWS * K_DIM) return;
    uint2 key = g_keys[t];
    uint32_t o0, o1;
    threefry2x32(key.x, key.y, 0u, (uint32_t)i, o0, o1);
    uint32_t bits = o0 ^ o1;
    float r = __uint_as_float((bits >> 9) | 0x3f800000u) - 1.0f;  // [0,1)
    float x = inp[i];
    float sp = 0.5f;
    if (r * 2.0f <= fabsf(x)) {
        if (x > 0.0f)      sp = 1.0f;
        else if (x < 0.0f) sp = 0.0f;
    }
    g_sp[i] = sp;
}

// ---------------- LIF epilogue helper (per element, fixed fp32 order) -------
__device__ __forceinline__ void lif_update(size_t idx, float z) {
    const float cL = 0.95f;
    const float cI = 0.05000000074505806f;     // float32(1.0 - 0.95)
    float m = g_mem1[idx];
    m = __fadd_rn(__fmul_rn(cL, m), __fmul_rn(cI, z));
    float thr = __fadd_rn(m, -1.0f);
    if (thr > 0.0f) { g_S[idx] += 1.0f; m = __fadd_rn(m, -1.0f); }
    g_mem1[idx] = m;
}

// ---------------- fused GEMM + LIF update per step --------------------------
// Z[b,j] = sp[b,:] . w1[j,:]  with Eigen kc=248 panel folds (248/496/744/784).
// bx<6 : full 128-col tile.  bx==6 : narrow 32-col tile (cols 768..799),
// ~0.27x duration -> heterogeneous blocks pack the 148-SM schedule tightly.
__global__ __launch_bounds__(256) void k_step(const float* __restrict__ w1) {
    __shared__ float As[8][128];
    __shared__ float Bs[8][128];

    const int tid = threadIdx.x;
    const int bx  = blockIdx.x;            // N tile (0..6)
    const int by  = blockIdx.y;            // M tile (0..63)
    const int lr  = tid >> 1;              // load row within tile (0..127)
    const int lc  = (tid & 1) << 2;        // load col offset (0 or 4)

    const int rowA = by * 128 + lr;
    const float* Aptr = g_sp + (size_t)rowA * K_DIM;

    if (bx < 6) {
        // ---------------- full path: 128x128 tile, 8x8 per thread ----------
        const int tx = tid & 15;
        const int ty = tid >> 4;
        const float* Bptr = w1 + (size_t)(bx * 128 + lr) * K_DIM;

        float csum[8][8], acc[8][8];
        #pragma unroll
        for (int i = 0; i < 8; i++)
            #pragma unroll
            for (int j = 0; j < 8; j++) { csum[i][j] = 0.0f; acc[i][j] = 0.0f; }

        int next_fold = 248;
        #pragma unroll 1
        for (int t = 0; t < NTILES; t++) {
            const int k0 = t * 8;
            float4 av = *(const float4*)(Aptr + k0 + lc);
            float4 bv = *(const float4*)(Bptr + k0 + lc);
            __syncthreads();
            As[lc + 0][lr] = av.x; As[lc + 1][lr] = av.y;
            As[lc + 2][lr] = av.z; As[lc + 3][lr] = av.w;
            Bs[lc + 0][lr] = bv.x; Bs[lc + 1][lr] = bv.y;
            Bs[lc + 2][lr] = bv.z; Bs[lc + 3][lr] = bv.w;
            __syncthreads();

            #pragma unroll
            for (int kk = 0; kk < 8; kk++) {
                float4 a0 = *(const float4*)&As[kk][ty * 8];
                float4 a1 = *(const float4*)&As[kk][ty * 8 + 4];
                float4 b0 = *(const float4*)&Bs[kk][tx * 8];
                float4 b1 = *(const float4*)&Bs[kk][tx * 8 + 4];
                float a[8] = {a0.x, a0.y, a0.z, a0.w, a1.x, a1.y, a1.z, a1.w};
                float b[8] = {b0.x, b0.y, b0.z, b0.w, b1.x, b1.y, b1.z, b1.w};
                #pragma unroll
                for (int i = 0; i < 8; i++)
                    #pragma unroll
                    for (int j = 0; j < 8; j++)
                        acc[i][j] = __fmaf_rn(a[i], b[j], acc[i][j]);
            }

            const int kend = k0 + 8;
            if (kend == next_fold || kend == K_DIM) {
                #pragma unroll
                for (int i = 0; i < 8; i++)
                    #pragma unroll
                    for (int j = 0; j < 8; j++) {
                        csum[i][j] = __fadd_rn(csum[i][j], acc[i][j]);
                        acc[i][j] = 0.0f;
                    }
                next_fold += 248;
            }
        }

        const int mbase = by * 128 + ty * 8;
        const int nbase = bx * 128 + tx * 8;
        #pragma unroll
        for (int i = 0; i < 8; i++)
            #pragma unroll
            for (int j = 0; j < 8; j++)
                lif_update((size_t)(mbase + i) * N_DIM + (nbase + j), csum[i][j]);
    } else {
        // ---------------- narrow path: 128x32 tile (cols 768..799) ---------
        // thread layout: tx 0..15 covers 32 cols (2 each), ty 0..15 rows (8 each)
        const int tx = tid & 15;
        const int ty = tid >> 4;

        float csum[8][2], acc[8][2];
        #pragma unroll
        for (int i = 0; i < 8; i++)
            #pragma unroll
            for (int j = 0; j < 2; j++) { csum[i][j] = 0.0f; acc[i][j] = 0.0f; }

        int next_fold = 248;
        #pragma unroll 1
        for (int t = 0; t < NTILES; t++) {
            const int k0 = t * 8;
            float4 av = *(const float4*)(Aptr + k0 + lc);
            float4 bv = make_float4(0.f, 0.f, 0.f, 0.f);
            if (lr < 32)
                bv = *(const float4*)(w1 + (size_t)(768 + lr) * K_DIM + k0 + lc);
            __syncthreads();
            As[lc + 0][lr] = av.x; As[lc + 1][lr] = av.y;
            As[lc + 2][lr] = av.z; As[lc + 3][lr] = av.w;
            if (lr < 32) {
                Bs[lc + 0][lr] = bv.x; Bs[lc + 1][lr] = bv.y;
                Bs[lc + 2][lr] = bv.z; Bs[lc + 3][lr] = bv.w;
            }
            __syncthreads();

            #pragma unroll
            for (int kk = 0; kk < 8; kk++) {
                float4 a0 = *(const float4*)&As[kk][ty * 8];
                float4 a1 = *(const float4*)&As[kk][ty * 8 + 4];
                float b0 = Bs[kk][tx * 2];
                float b1 = Bs[kk][tx * 2 + 1];
                float a[8] = {a0.x, a0.y, a0.z, a0.w, a1.x, a1.y, a1.z, a1.w};
                #pragma unroll
                for (int i = 0; i < 8; i++) {
                    acc[i][0] = __fmaf_rn(a[i], b0, acc[i][0]);
                    acc[i][1] = __fmaf_rn(a[i], b1, acc[i][1]);
                }
            }

            const int kend = k0 + 8;
            if (kend == next_fold || kend == K_DIM) {
                #pragma unroll
                for (int i = 0; i < 8; i++)
                    #pragma unroll
                    for (int j = 0; j < 2; j++) {
                        csum[i][j] = __fadd_rn(csum[i][j], acc[i][j]);
                        acc[i][j] = 0.0f;
                    }
                next_fold += 248;
            }
        }

        const int mbase = by * 128 + ty * 8;
        const int nbase = 768 + tx * 2;
        #pragma unroll
        for (int i = 0; i < 8; i++)
            #pragma unroll
            for (int j = 0; j < 2; j++)
                lif_update((size_t)(mbase + i) * N_DIM + (nbase + j), csum[i][j]);
    }
}

// ---------------- final: out = (S @ w2^T) / 25 ------------------------------
__global__ void k_final(const float* __restrict__ w2, float* __restrict__ out) {
    int gw   = (blockIdx.x * blockDim.x + threadIdx.x) >> 5;
    int lane = threadIdx.x & 31;
    if (gw >= B_ROWS * 10) return;
    int b = gw / 10, c = gw % 10;
    const float* srow = g_S + (size_t)b * N_DIM;
    const float* wrow = w2 + (size_t)c * N_DIM;
    float s = 0.0f;
    for (int k = lane; k < N_DIM; k += 32) s += srow[k] * wrow[k];
    #pragma unroll
    for (int off = 16; off; off >>= 1) s += __shfl_xor_sync(0xFFFFFFFFu, s, off);
    if (lane == 0) out[(size_t)b * 10 + c] = s / 25.0f;
}

// ---------------- launch ----------------------------------------------------
extern "C" void kernel_launch(void* const* d_in, const int* in_sizes, int n_in,
                              void* d_out, int out_size) {
    const float* inp = (const float*)d_in[0];   // [8192, 784]
    const float* w1  = (const float*)d_in[1];   // [800, 784]
    const float* w2  = (const float*)d_in[2];   // [10, 800]
    float* out = (float*)d_out;                 // [8192, 10]

    k_init<<<1, 32>>>();
    k_zero<<<(B_ROWS * N_DIM + 255) / 256, 256>>>();

    for (int t = 0; t < NSTEPS; t++) {
        k_spike<<<(B_ROWS * K_DIM + 255) / 256, 256>>>(inp, t);
        k_step<<<dim3(7, 64), 256>>>(w1);
    }

    k_final<<<(B_ROWS * 10 * 32 + 255) / 256, 256>>>(w2, out);
}

// round 7
// speedup vs baseline: 1.1342x; 1.1342x over previous
#include <cuda_runtime.h>
#include <cstdint>

#define B_ROWS 8192
#define K_DIM  784
#define N_DIM  800
#define NSTEPS 25
#define NTILES (K_DIM / 8)   // 98

// ---------------- device scratch (static globals: no runtime allocation) ----
__device__ float g_sp  [B_ROWS * K_DIM];   // Poisson spike matrix {0, 0.5, 1}
__device__ float g_mem1[B_ROWS * N_DIM];   // membrane potential
__device__ float g_S   [B_ROWS * N_DIM];   // spike counts
__device__ uint2 g_keys[NSTEPS];           // per-step threefry keys

// ---------------- threefry2x32 (matches JAX, 20 rounds) --------------------
__device__ __forceinline__ void threefry2x32(uint32_t k0, uint32_t k1,
                                             uint32_t x0, uint32_t x1,
                                             uint32_t &o0, uint32_t &o1) {
    uint32_t ks0 = k0, ks1 = k1, ks2 = 0x1BD11BDAu ^ k0 ^ k1;
    x0 += ks0; x1 += ks1;
#define TF_R(r) { x0 += x1; x1 = __funnelshift_l(x1, x1, (r)); x1 ^= x0; }
    TF_R(13) TF_R(15) TF_R(26) TF_R(6)
    x0 += ks1; x1 += ks2 + 1u;
    TF_R(17) TF_R(29) TF_R(16) TF_R(24)
    x0 += ks2; x1 += ks0 + 2u;
    TF_R(13) TF_R(15) TF_R(26) TF_R(6)
    x0 += ks0; x1 += ks1 + 3u;
    TF_R(17) TF_R(29) TF_R(16) TF_R(24)
    x0 += ks1; x1 += ks2 + 4u;
    TF_R(13) TF_R(15) TF_R(26) TF_R(6)
    x0 += ks2; x1 += ks0 + 5u;
#undef TF_R
    o0 = x0; o1 = x1;
}

// ---------------- init: per-step keys ---------------------------------------
__global__ void k_init() {
    int t = threadIdx.x;
    if (t < NSTEPS) {
        uint32_t o0, o1;
        threefry2x32(0u, 42u, 0u, (uint32_t)t, o0, o1);
        g_keys[t] = make_uint2(o0, o1);
    }
}

// ---------------- zero state ------------------------------------------------
__global__ void k_zero() {
    int i = blockIdx.x * blockDim.x + threadIdx.x;
    if (i < B_ROWS * N_DIM) { g_mem1[i] = 0.0f; g_S[i] = 0.0f; }
}

// ---------------- per-step spike (Poisson) generation -----------------------
__global__ void k_spike(const float* __restrict__ inp, int t) {
    int i = blockIdx.x * blockDim.x + threadIdx.x;
    if (i >= B_ROWS * K_DIM) return;
    uint2 key = g_keys[t];
    uint32_t o0, o1;
    threefry2x32(key.x, key.y, 0u, (uint32_t)i, o0, o1);
    uint32_t bits = o0 ^ o1;
    float r = __uint_as_float((bits >> 9) | 0x3f800000u) - 1.0f;  // [0,1)
    float x = inp[i];
    float sp = 0.5f;
    if (r * 2.0f <= fabsf(x)) {
        if (x > 0.0f)      sp = 1.0f;
        else if (x < 0.0f) sp = 0.0f;
    }
    g_sp[i] = sp;
}

// ---------------- fused GEMM + LIF update per step --------------------------
// Tile 128(M) x 64(N), 128 threads, 2 blocks/SM. 8x8 per-thread microtile.
// Z[b,j] = sp[b,:] . w1[j,:]  with Eigen kc=248 panel folds (248/496/744/784).
// mem1 = 0.95*mem1 + 0.05*Z; spike if mem1-1>0; reset; count.
__global__ __launch_bounds__(128, 2) void k_step(const float* __restrict__ w1) {
    __shared__ float As[8][128];
    __shared__ float Bs[8][64];

    const int tid = threadIdx.x;
    const int bx  = blockIdx.x;            // N tile (0..12), 64 cols each
    const int by  = blockIdx.y;            // M tile (0..63), 128 rows each
    const int tx  = tid & 7;               // 8 cols per thread
    const int ty  = tid >> 3;              // 0..15, 8 rows per thread

    // A loads: one row per thread (row tid), 8 k-floats = 2 float4
    const int rowA = by * 128 + tid;
    const float* Aptr = g_sp + (size_t)rowA * K_DIM;
    // B loads: row tid>>1 (0..63), float4 at (tid&1)*4
    const int lrB = tid >> 1;
    const int lcB = (tid & 1) << 2;
    const int rowB = bx * 64 + lrB;
    const bool bok = (rowB < N_DIM);
    const float* Bptr = w1 + (size_t)rowB * K_DIM;

    float csum[8][8], acc[8][8];
    #pragma unroll
    for (int i = 0; i < 8; i++)
        #pragma unroll
        for (int j = 0; j < 8; j++) { csum[i][j] = 0.0f; acc[i][j] = 0.0f; }

    int next_fold = 248;
    #pragma unroll 1
    for (int t = 0; t < NTILES; t++) {
        const int k0 = t * 8;
        float4 av0 = *(const float4*)(Aptr + k0);
        float4 av1 = *(const float4*)(Aptr + k0 + 4);
        float4 bv  = bok ? *(const float4*)(Bptr + k0 + lcB)
                         : make_float4(0.f, 0.f, 0.f, 0.f);
        __syncthreads();
        As[0][tid] = av0.x; As[1][tid] = av0.y;
        As[2][tid] = av0.z; As[3][tid] = av0.w;
        As[4][tid] = av1.x; As[5][tid] = av1.y;
        As[6][tid] = av1.z; As[7][tid] = av1.w;
        Bs[lcB + 0][lrB] = bv.x; Bs[lcB + 1][lrB] = bv.y;
        Bs[lcB + 2][lrB] = bv.z; Bs[lcB + 3][lrB] = bv.w;
        __syncthreads();

        #pragma unroll
        for (int kk = 0; kk < 8; kk++) {
            float4 a0 = *(const float4*)&As[kk][ty * 8];
            float4 a1 = *(const float4*)&As[kk][ty * 8 + 4];
            float4 b0 = *(const float4*)&Bs[kk][tx * 8];
            float4 b1 = *(const float4*)&Bs[kk][tx * 8 + 4];
            float a[8] = {a0.x, a0.y, a0.z, a0.w, a1.x, a1.y, a1.z, a1.w};
            float b[8] = {b0.x, b0.y, b0.z, b0.w, b1.x, b1.y, b1.z, b1.w};
            #pragma unroll
            for (int i = 0; i < 8; i++)
                #pragma unroll
                for (int j = 0; j < 8; j++)
                    acc[i][j] = __fmaf_rn(a[i], b[j], acc[i][j]);
        }

        const int kend = k0 + 8;
        if (kend == next_fold || kend == K_DIM) {
            #pragma unroll
            for (int i = 0; i < 8; i++)
                #pragma unroll
                for (int j = 0; j < 8; j++) {
                    csum[i][j] = __fadd_rn(csum[i][j], acc[i][j]);
                    acc[i][j] = 0.0f;
                }
            next_fold += 248;
        }
    }

    // epilogue: LIF update (non-contracted mul/mul/add, XLA elementwise order)
    const float cL = 0.95f;
    const float cI = 0.05000000074505806f;     // float32(1.0 - 0.95)
    const int mbase = by * 128 + ty * 8;
    const int nbase = bx * 64 + tx * 8;
    #pragma unroll
    for (int i = 0; i < 8; i++) {
        int b = mbase + i;
        #pragma unroll
        for (int j = 0; j < 8; j++) {
            int c = nbase + j;
            if (c < N_DIM) {
                size_t idx = (size_t)b * N_DIM + c;
                float m = g_mem1[idx];
                m = __fadd_rn(__fmul_rn(cL, m), __fmul_rn(cI, csum[i][j]));
                float thr = __fadd_rn(m, -1.0f);
                if (thr > 0.0f) { g_S[idx] += 1.0f; m = __fadd_rn(m, -1.0f); }
                g_mem1[idx] = m;
            }
        }
    }
}

// ---------------- final: out = (S @ w2^T) / 25 ------------------------------
__global__ void k_final(const float* __restrict__ w2, float* __restrict__ out) {
    int gw   = (blockIdx.x * blockDim.x + threadIdx.x) >> 5;
    int lane = threadIdx.x & 31;
    if (gw >= B_ROWS * 10) return;
    int b = gw / 10, c = gw % 10;
    const float* srow = g_S + (size_t)b * N_DIM;
    const float* wrow = w2 + (size_t)c * N_DIM;
    float s = 0.0f;
    for (int k = lane; k < N_DIM; k += 32) s += srow[k] * wrow[k];
    #pragma unroll
    for (int off = 16; off; off >>= 1) s += __shfl_xor_sync(0xFFFFFFFFu, s, off);
    if (lane == 0) out[(size_t)b * 10 + c] = s / 25.0f;
}

// ---------------- launch ----------------------------------------------------
extern "C" void kernel_launch(void* const* d_in, const int* in_sizes, int n_in,
                              void* d_out, int out_size) {
    const float* inp = (const float*)d_in[0];   // [8192, 784]
    const float* w1  = (const float*)d_in[1];   // [800, 784]
    const float* w2  = (const float*)d_in[2];   // [10, 800]
    float* out = (float*)d_out;                 // [8192, 10]

    k_init<<<1, 32>>>();
    k_zero<<<(B_ROWS * N_DIM + 255) / 256, 256>>>();

    for (int t = 0; t < NSTEPS; t++) {
        k_spike<<<(B_ROWS * K_DIM + 255) / 256, 256>>>(inp, t);
        k_step<<<dim3(13, 64), 128>>>(w1);
    }

    k_final<<<(B_ROWS * 10 * 32 + 255) / 256, 256>>>(w2, out);
}

// round 8
// speedup vs baseline: 1.4098x; 1.2430x over previous
#include <cuda_runtime.h>
#include <cstdint>

#define B_ROWS 8192
#define K_DIM  784
#define N_DIM  800
#define NSTEPS 25
#define NTILES (K_DIM / 8)            // 98
#define STEP_ELEMS (B_ROWS * K_DIM)   // 6422528
#define M_TOTAL (NSTEPS * B_ROWS)     // 204800
#define Z_STEP  (B_ROWS * N_DIM)      // 6553600

// ---------------- device scratch (static globals: no runtime allocation) ----
__device__ float g_sp[(size_t)NSTEPS * STEP_ELEMS];  // all 25 spike matrices
__device__ float g_Z [(size_t)NSTEPS * Z_STEP];      // all 25 pre-activations
__device__ float g_S [Z_STEP];                       // spike counts
__device__ uint2 g_keys[NSTEPS];                     // per-step threefry keys

// ---------------- threefry2x32 (matches JAX, 20 rounds) --------------------
__device__ __forceinline__ void threefry2x32(uint32_t k0, uint32_t k1,
                                             uint32_t x0, uint32_t x1,
                                             uint32_t &o0, uint32_t &o1) {
    uint32_t ks0 = k0, ks1 = k1, ks2 = 0x1BD11BDAu ^ k0 ^ k1;
    x0 += ks0; x1 += ks1;
#define TF_R(r) { x0 += x1; x1 = __funnelshift_l(x1, x1, (r)); x1 ^= x0; }
    TF_R(13) TF_R(15) TF_R(26) TF_R(6)
    x0 += ks1; x1 += ks2 + 1u;
    TF_R(17) TF_R(29) TF_R(16) TF_R(24)
    x0 += ks2; x1 += ks0 + 2u;
    TF_R(13) TF_R(15) TF_R(26) TF_R(6)
    x0 += ks0; x1 += ks1 + 3u;
    TF_R(17) TF_R(29) TF_R(16) TF_R(24)
    x0 += ks1; x1 += ks2 + 4u;
    TF_R(13) TF_R(15) TF_R(26) TF_R(6)
    x0 += ks2; x1 += ks0 + 5u;
#undef TF_R
    o0 = x0; o1 = x1;
}

// ---------------- init: per-step keys ---------------------------------------
__global__ void k_init() {
    int t = threadIdx.x;
    if (t < NSTEPS) {
        uint32_t o0, o1;
        threefry2x32(0u, 42u, 0u, (uint32_t)t, o0, o1);
        g_keys[t] = make_uint2(o0, o1);
    }
}

// ---------------- spike generation for ALL steps ----------------------------
// blockIdx.y = step t; each thread makes 4 consecutive elements (float4 store)
__global__ void k_spike_all(const float* __restrict__ inp) {
    const int t = blockIdx.y;
    const uint32_t e0 = (blockIdx.x * blockDim.x + threadIdx.x) * 4u;
    if (e0 >= STEP_ELEMS) return;
    const uint2 key = g_keys[t];
    float4 sp4;
    float* spp = &sp4.x;
    const float4 x4 = *(const float4*)(inp + e0);
    const float* xp = &x4.x;
    #pragma unroll
    for (int c = 0; c < 4; c++) {
        uint32_t o0, o1;
        threefry2x32(key.x, key.y, 0u, e0 + (uint32_t)c, o0, o1);
        uint32_t bits = o0 ^ o1;
        float r = __uint_as_float((bits >> 9) | 0x3f800000u) - 1.0f;  // [0,1)
        float x = xp[c];
        float sp = 0.5f;
        if (r * 2.0f <= fabsf(x)) {
            if (x > 0.0f)      sp = 1.0f;
            else if (x < 0.0f) sp = 0.0f;
        }
        spp[c] = sp;
    }
    *(float4*)(g_sp + (size_t)t * STEP_ELEMS + e0) = sp4;
}

// ---------------- mega GEMM: Z[mt, j] = sp[mt,:] . w1[j,:] ------------------
// M = 204800, N = 800 tiled 128 x 160 (exactly 1600 x 5 tiles, no padding).
// 256 threads, microtile 8 rows x 10 cols (cols tx + 16c).
// Eigen kc=248 panel folds at k = 248 / 496 / 744 / 784 (bit-exact chains).
__global__ __launch_bounds__(256) void k_gemm(const float* __restrict__ w1) {
    __shared__ float As[8][128];
    __shared__ float Bs[8][160];

    const int tid = threadIdx.x;
    const int bx  = blockIdx.x;            // N tile (0..4), 160 cols
    const int by  = blockIdx.y;            // M tile (0..1599), 128 rows
    const int tx  = tid & 15;              // cols tx + 16c, c = 0..9
    const int ty  = tid >> 4;              // rows ty*8 .. +7

    // A loads: 128 rows x 8 k = 256 float4; thread t -> row t>>1, col (t&1)*4
    const int lrA = tid >> 1;
    const int lcA = (tid & 1) << 2;
    const float* Aptr = g_sp + (size_t)(by * 128 + lrA) * K_DIM + lcA;
    // B loads: 160 rows x 8 k = 320 float4; thread t -> task t (+ task 256+t if t<64)
    const int lrB0 = tid >> 1;
    const int lcB0 = (tid & 1) << 2;
    const int lrB1 = (tid + 256) >> 1;     // 128..159 for tid < 64
    const int lcB1 = (tid & 1) << 2;
    const float* BptrBase = w1 + (size_t)(bx * 160) * K_DIM;

    float csum[8][10], acc[8][10];
    #pragma unroll
    for (int i = 0; i < 8; i++)
        #pragma unroll
        for (int c = 0; c < 10; c++) { csum[i][c] = 0.0f; acc[i][c] = 0.0f; }

    int next_fold = 248;
    #pragma unroll 1
    for (int t = 0; t < NTILES; t++) {
        const int k0 = t * 8;
        float4 av = *(const float4*)(Aptr + k0);
        float4 bv0 = *(const float4*)(BptrBase + (size_t)lrB0 * K_DIM + k0 + lcB0);
        float4 bv1;
        if (tid < 64)
            bv1 = *(const float4*)(BptrBase + (size_t)lrB1 * K_DIM + k0 + lcB1);
        __syncthreads();
        As[lcA + 0][lrA] = av.x; As[lcA + 1][lrA] = av.y;
        As[lcA + 2][lrA] = av.z; As[lcA + 3][lrA] = av.w;
        Bs[lcB0 + 0][lrB0] = bv0.x; Bs[lcB0 + 1][lrB0] = bv0.y;
        Bs[lcB0 + 2][lrB0] = bv0.z; Bs[lcB0 + 3][lrB0] = bv0.w;
        if (tid < 64) {
            Bs[lcB1 + 0][lrB1] = bv1.x; Bs[lcB1 + 1][lrB1] = bv1.y;
            Bs[lcB1 + 2][lrB1] = bv1.z; Bs[lcB1 + 3][lrB1] = bv1.w;
        }
        __syncthreads();

        #pragma unroll
        for (int kk = 0; kk < 8; kk++) {
            float4 a0 = *(const float4*)&As[kk][ty * 8];
            float4 a1 = *(const float4*)&As[kk][ty * 8 + 4];
            float a[8] = {a0.x, a0.y, a0.z, a0.w, a1.x, a1.y, a1.z, a1.w};
            float b[10];
            #pragma unroll
            for (int c = 0; c < 10; c++) b[c] = Bs[kk][tx + 16 * c];
            #pragma unroll
            for (int i = 0; i < 8; i++)
                #pragma unroll
                for (int c = 0; c < 10; c++)
                    acc[i][c] = __fmaf_rn(a[i], b[c], acc[i][c]);
        }

        const int kend = k0 + 8;
        if (kend == next_fold || kend == K_DIM) {
            #pragma unroll
            for (int i = 0; i < 8; i++)
                #pragma unroll
                for (int c = 0; c < 10; c++) {
                    csum[i][c] = __fadd_rn(csum[i][c], acc[i][c]);
                    acc[i][c] = 0.0f;
                }
            next_fold += 248;
        }
    }

    // store Z (plain GEMM output; LIF is a separate pass)
    const int mbase = by * 128 + ty * 8;
    const int nbase = bx * 160 + tx;
    #pragma unroll
    for (int i = 0; i < 8; i++) {
        float* zrow = g_Z + (size_t)(mbase + i) * N_DIM + nbase;
        #pragma unroll
        for (int c = 0; c < 10; c++)
            zrow[16 * c] = csum[i][c];
    }
}

// ---------------- LIF recurrence: registers only, one thread per (b,j) ------
// m_t = 0.95*m + 0.05*Z_t; spike if m-1>0 -> count, m -= 1.  S written once.
__global__ void k_lif() {
    const int idx = blockIdx.x * blockDim.x + threadIdx.x;
    if (idx >= Z_STEP) return;
    const float cL = 0.95f;
    const float cI = 0.05000000074505806f;     // float32(1.0 - 0.95)
    float m = 0.0f, cnt = 0.0f;
    #pragma unroll 1
    for (int t = 0; t < NSTEPS; t++) {
        float z = g_Z[(size_t)t * Z_STEP + idx];
        m = __fadd_rn(__fmul_rn(cL, m), __fmul_rn(cI, z));
        float thr = __fadd_rn(m, -1.0f);
        if (thr > 0.0f) { cnt += 1.0f; m = __fadd_rn(m, -1.0f); }
    }
    g_S[idx] = cnt;
}

// ---------------- final: out = (S @ w2^T) / 25 ------------------------------
__global__ void k_final(const float* __restrict__ w2, float* __restrict__ out) {
    int gw   = (blockIdx.x * blockDim.x + threadIdx.x) >> 5;
    int lane = threadIdx.x & 31;
    if (gw >= B_ROWS * 10) return;
    int b = gw / 10, c = gw % 10;
    const float* srow = g_S + (size_t)b * N_DIM;
    const float* wrow = w2 + (size_t)c * N_DIM;
    float s = 0.0f;
    for (int k = lane; k < N_DIM; k += 32) s += srow[k] * wrow[k];
    #pragma unroll
    for (int off = 16; off; off >>= 1) s += __shfl_xor_sync(0xFFFFFFFFu, s, off);
    if (lane == 0) out[(size_t)b * 10 + c] = s / 25.0f;
}

// ---------------- launch ----------------------------------------------------
extern "C" void kernel_launch(void* const* d_in, const int* in_sizes, int n_in,
                              void* d_out, int out_size) {
    const float* inp = (const float*)d_in[0];   // [8192, 784]
    const float* w1  = (const float*)d_in[1];   // [800, 784]
    const float* w2  = (const float*)d_in[2];   // [10, 800]
    float* out = (float*)d_out;                 // [8192, 10]

    k_init<<<1, 32>>>();
    k_spike_all<<<dim3(STEP_ELEMS / 4 / 256, NSTEPS), 256>>>(inp);
    k_gemm<<<dim3(5, 1600), 256>>>(w1);
    k_lif<<<(Z_STEP + 255) / 256, 256>>>();
    k_final<<<(B_ROWS * 10 * 32 + 255) / 256, 256>>>(w2, out);
}

// round 9
// speedup vs baseline: 1.8039x; 1.2795x over previous
#include <cuda_runtime.h>
#include <cuda_bf16.h>
#include <cstdint>

#define B_ROWS 8192
#define K_DIM  784
#define N_DIM  800
#define N_PAD  896
#define NSTEPS 25
#define STEP_ELEMS (B_ROWS * K_DIM)       // 6422528
#define M_TOTAL (NSTEPS * B_ROWS)         // 204800
#define Z_STEP  (B_ROWS * N_DIM)          // 6553600
#define WL_CAP  (1 << 20)
#define DELTA   1e-4f

// ---------------- device scratch ------------------------------------------
__device__ __nv_bfloat16 g_sph[(size_t)NSTEPS * STEP_ELEMS];       // sp bf16
__device__ uint32_t      g_spc[(size_t)NSTEPS * STEP_ELEMS / 16];  // 2-bit codes
__device__ float         g_Z[(size_t)NSTEPS * Z_STEP];             // fast Z
__device__ float         g_S[Z_STEP];                              // spike counts
__device__ __nv_bfloat16 g_w1s[3][(size_t)N_PAD * K_DIM];          // w1 bf16 splits
__device__ uint2         g_keys[NSTEPS];
__device__ int           g_cnt;
__device__ int           g_wl[WL_CAP];

// ---------------- threefry2x32 (matches JAX, 20 rounds) -------------------
__device__ __forceinline__ void threefry2x32(uint32_t k0, uint32_t k1,
                                             uint32_t x0, uint32_t x1,
                                             uint32_t &o0, uint32_t &o1) {
    uint32_t ks0 = k0, ks1 = k1, ks2 = 0x1BD11BDAu ^ k0 ^ k1;
    x0 += ks0; x1 += ks1;
#define TF_R(r) { x0 += x1; x1 = __funnelshift_l(x1, x1, (r)); x1 ^= x0; }
    TF_R(13) TF_R(15) TF_R(26) TF_R(6)
    x0 += ks1; x1 += ks2 + 1u;
    TF_R(17) TF_R(29) TF_R(16) TF_R(24)
    x0 += ks2; x1 += ks0 + 2u;
    TF_R(13) TF_R(15) TF_R(26) TF_R(6)
    x0 += ks0; x1 += ks1 + 3u;
    TF_R(17) TF_R(29) TF_R(16) TF_R(24)
    x0 += ks1; x1 += ks2 + 4u;
    TF_R(13) TF_R(15) TF_R(26) TF_R(6)
    x0 += ks2; x1 += ks0 + 5u;
#undef TF_R
    o0 = x0; o1 = x1;
}

__global__ void k_init() {
    int t = threadIdx.x;
    if (t < NSTEPS) {
        uint32_t o0, o1;
        threefry2x32(0u, 42u, 0u, (uint32_t)t, o0, o1);
        g_keys[t] = make_uint2(o0, o1);
    }
    if (t == 0) g_cnt = 0;
}

// ---------------- w1 -> 3 exact bf16 splits (rows >= 800 zero-padded) ------
__global__ void k_wsplit(const float* __restrict__ w1) {
    int idx = blockIdx.x * blockDim.x + threadIdx.x;
    if (idx >= N_PAD * K_DIM) return;
    int n = idx / K_DIM;
    float w = (n < N_DIM) ? w1[idx - (n - n) * 0 + 0 * 0 + (size_t)n * K_DIM + (idx % K_DIM)] : 0.0f;
    // (n < N_DIM) path: w1 is [800][784] row-major; idx maps directly
    if (n < N_DIM) w = w1[idx];
    __nv_bfloat16 h0 = __float2bfloat16_rn(w);
    float r1 = w - __bfloat162float(h0);
    __nv_bfloat16 h1 = __float2bfloat16_rn(r1);
    float r2 = r1 - __bfloat162float(h1);
    __nv_bfloat16 h2 = __float2bfloat16_rn(r2);
    g_w1s[0][idx] = h0; g_w1s[1][idx] = h1; g_w1s[2][idx] = h2;
}

// ---------------- spike generation: bf16 + 2-bit codes, 16 elems/thread ----
__global__ void k_spike_all(const float* __restrict__ inp) {
    const int t = blockIdx.y;
    const uint32_t e0 = (blockIdx.x * blockDim.x + threadIdx.x) * 16u;
    if (e0 >= STEP_ELEMS) return;
    const uint2 key = g_keys[t];
    uint32_t codes = 0;
    __nv_bfloat16 sb[16];
    #pragma unroll
    for (int c = 0; c < 16; c++) {
        uint32_t o0, o1;
        threefry2x32(key.x, key.y, 0u, e0 + (uint32_t)c, o0, o1);
        uint32_t bits = o0 ^ o1;
        float r = __uint_as_float((bits >> 9) | 0x3f800000u) - 1.0f;
        float x = inp[e0 + c];
        uint32_t code = 1u;                          // sp = 0.5
        if (r * 2.0f <= fabsf(x)) {
            if (x > 0.0f)      code = 2u;            // sp = 1
            else if (x < 0.0f) code = 0u;            // sp = 0
        }
        codes |= code << (2 * c);
        unsigned short hb = code ? (unsigned short)(0x3E80u + (code << 7)) : 0;
        sb[c] = __ushort_as_bfloat16(hb);
    }
    size_t base = (size_t)t * STEP_ELEMS + e0;
    *(uint4*)(g_sph + base)     = *(uint4*)&sb[0];
    *(uint4*)(g_sph + base + 8) = *(uint4*)&sb[8];
    g_spc[base >> 4] = codes;
}

// ---------------- fast GEMM: Z = sp @ (w0+w1+w2)^T via mma.sync bf16 -------
// Block 128M x 128N, 8 warps (2M x 4N), warp tile 64x32. K = 3 passes x 49x16.
__device__ __forceinline__ void ldsm_x4(uint32_t* r, uint32_t addr) {
    asm volatile("ldmatrix.sync.aligned.m8n8.x4.shared.b16 {%0,%1,%2,%3}, [%4];"
                 : "=r"(r[0]), "=r"(r[1]), "=r"(r[2]), "=r"(r[3]) : "r"(addr));
}
__device__ __forceinline__ void mma16816(float* c, const uint32_t* a,
                                         uint32_t b0, uint32_t b1) {
    asm volatile(
        "mma.sync.aligned.m16n8k16.row.col.f32.bf16.bf16.f32 "
        "{%0,%1,%2,%3},{%4,%5,%6,%7},{%8,%9},{%0,%1,%2,%3};"
        : "+f"(c[0]), "+f"(c[1]), "+f"(c[2]), "+f"(c[3])
        : "r"(a[0]), "r"(a[1]), "r"(a[2]), "r"(a[3]), "r"(b0), "r"(b1));
}

__global__ __launch_bounds__(256) void k_gemm_f() {
    __shared__ __align__(16) char smem[2 * 128 * 48];   // A rows then B rows, 48B stride

    const int tid  = threadIdx.x;
    const int bx   = blockIdx.x;               // 0..6  (N, 128 each, padded to 896)
    const int by   = blockIdx.y;               // 0..1599 (M, 128 each)
    const int warp = tid >> 5, lane = tid & 31;
    const int wm = (warp & 1) * 64;            // warp M offset
    const int wn = (warp >> 1) * 32;           // warp N offset

    const uint32_t sA = (uint32_t)__cvta_generic_to_shared(smem);
    const uint32_t sB = sA + 128 * 48;

    // LDSM source addresses (loop-invariant)
    uint32_t addrA[4], addrB[2];
    {
        int rA = (lane & 7) + ((lane >> 3) & 1) * 8;
        int hA = lane >> 4;
        #pragma unroll
        for (int mi = 0; mi < 4; mi++)
            addrA[mi] = sA + (uint32_t)(wm + mi * 16 + rA) * 48 + hA * 16;
        int rB = (lane & 7) + ((lane >> 4) & 1) * 8;
        int hB = (lane >> 3) & 1;
        #pragma unroll
        for (int p = 0; p < 2; p++)
            addrB[p] = sB + (uint32_t)(wn + p * 16 + rB) * 48 + hB * 16;
    }

    const int rowL = tid >> 1;                 // 0..127 load row
    const int half = tid & 1;                  // 16B half
    const __nv_bfloat16* Abase = g_sph + (size_t)(by * 128) * K_DIM;
    const int bn = bx * 128;

    float c[4][4][4];
    #pragma unroll
    for (int mi = 0; mi < 4; mi++)
        #pragma unroll
        for (int ni = 0; ni < 4; ni++)
            #pragma unroll
            for (int q = 0; q < 4; q++) c[mi][ni][q] = 0.0f;

    // prefetch iter 0
    uint4 av = *(const uint4*)(Abase + (size_t)rowL * K_DIM + half * 8);
    uint4 bv = *(const uint4*)(g_w1s[0] + (size_t)(bn + rowL) * K_DIM + half * 8);

    int s = 0, kt = 0;
    #pragma unroll 1
    for (int it = 0; it < 3 * 49; it++) {
        __syncthreads();
        *(uint4*)(smem + rowL * 48 + half * 16)            = av;
        *(uint4*)(smem + 128 * 48 + rowL * 48 + half * 16) = bv;
        __syncthreads();

        // prefetch next tile
        int kt2 = kt + 1, s2 = s;
        if (kt2 == 49) { kt2 = 0; s2++; }
        if (it + 1 < 3 * 49) {
            av = *(const uint4*)(Abase + (size_t)rowL * K_DIM + kt2 * 16 + half * 8);
            bv = *(const uint4*)(g_w1s[s2] + (size_t)(bn + rowL) * K_DIM + kt2 * 16 + half * 8);
        }

        uint32_t a[4][4], bf[2][4];
        #pragma unroll
        for (int mi = 0; mi < 4; mi++) ldsm_x4(a[mi], addrA[mi]);
        #pragma unroll
        for (int p = 0; p < 2; p++)    ldsm_x4(bf[p], addrB[p]);
        #pragma unroll
        for (int mi = 0; mi < 4; mi++)
            #pragma unroll
            for (int ni = 0; ni < 4; ni++)
                mma16816(c[mi][ni], a[mi], bf[ni >> 1][(ni & 1) * 2],
                         bf[ni >> 1][(ni & 1) * 2 + 1]);
        kt = kt2; s = s2;
    }

    // store Z_fast (guard padded cols)
    const int r0 = by * 128 + wm + (lane >> 2);
    const int c0 = bn + wn + (lane & 3) * 2;
    #pragma unroll
    for (int mi = 0; mi < 4; mi++)
        #pragma unroll
        for (int ni = 0; ni < 4; ni++) {
            int col = c0 + ni * 8;
            if (col < N_DIM) {
                int row = r0 + mi * 16;
                *(float2*)(g_Z + (size_t)row * N_DIM + col) =
                    make_float2(c[mi][ni][0], c[mi][ni][1]);
                *(float2*)(g_Z + (size_t)(row + 8) * N_DIM + col) =
                    make_float2(c[mi][ni][2], c[mi][ni][3]);
            }
        }
}

// ---------------- LIF + flagging (4 elems/thread) ---------------------------
__global__ void k_lif_flag() {
    const int q = blockIdx.x * blockDim.x + threadIdx.x;
    if (q >= Z_STEP / 4) return;
    const int idx = q * 4;
    const float cL = 0.95f;
    const float cI = 0.05000000074505806f;
    float m[4] = {0, 0, 0, 0}, cnt[4] = {0, 0, 0, 0};
    bool flag[4] = {false, false, false, false};
    #pragma unroll 1
    for (int t = 0; t < NSTEPS; t++) {
        float4 z4 = *(const float4*)(g_Z + (size_t)t * Z_STEP + idx);
        const float* zp = &z4.x;
        #pragma unroll
        for (int h = 0; h < 4; h++) {
            m[h] = __fadd_rn(__fmul_rn(cL, m[h]), __fmul_rn(cI, zp[h]));
            float thr = __fadd_rn(m[h], -1.0f);
            if (fabsf(thr) <= DELTA) flag[h] = true;
            if (thr > 0.0f) { cnt[h] += 1.0f; m[h] = __fadd_rn(m[h], -1.0f); }
        }
    }
    *(float4*)(g_S + idx) = make_float4(cnt[0], cnt[1], cnt[2], cnt[3]);
    #pragma unroll
    for (int h = 0; h < 4; h++)
        if (flag[h]) {
            int p = atomicAdd(&g_cnt, 1);
            if (p < WL_CAP) g_wl[p] = idx + h;
        }
}

// ---------------- exact recompute of flagged elements -----------------------
// Eigen kc=248 panel chains from 2-bit codes (validated fp32 ordering).
__global__ void k_exact(const float* __restrict__ w1) {
    const int i = blockIdx.x * blockDim.x + threadIdx.x;
    int n = g_cnt; if (n > WL_CAP) n = WL_CAP;
    if (i >= n) return;
    const int e = g_wl[i];
    const int b = e / N_DIM, j = e % N_DIM;
    const float* wrow = w1 + (size_t)j * K_DIM;
    const int pend[4] = {248, 496, 744, 784};
    const float cL = 0.95f;
    const float cI = 0.05000000074505806f;
    float m = 0.0f, cnt = 0.0f;
    #pragma unroll 1
    for (int t = 0; t < NSTEPS; t++) {
        const uint32_t* cw = g_spc + (((size_t)t * STEP_ELEMS + (size_t)b * K_DIM) >> 4);
        float csum = 0.0f;
        int k = 0;
        #pragma unroll 1
        for (int p = 0; p < 4; p++) {
            float acc = 0.0f;
            #pragma unroll 4
            for (; k < pend[p]; k++) {
                uint32_t code = (cw[k >> 4] >> ((k & 15) * 2)) & 3u;
                float sp = 0.5f * (float)code;
                acc = __fmaf_rn(sp, wrow[k], acc);
            }
            csum = __fadd_rn(csum, acc);
        }
        m = __fadd_rn(__fmul_rn(cL, m), __fmul_rn(cI, csum));
        float thr = __fadd_rn(m, -1.0f);
        if (thr > 0.0f) { cnt += 1.0f; m = __fadd_rn(m, -1.0f); }
    }
    g_S[e] = cnt;
}

// ---------------- final: out = (S @ w2^T) / 25 ------------------------------
__global__ void k_final(const float* __restrict__ w2, float* __restrict__ out) {
    int gw   = (blockIdx.x * blockDim.x + threadIdx.x) >> 5;
    int lane = threadIdx.x & 31;
    if (gw >= B_ROWS * 10) return;
    int b = gw / 10, c = gw % 10;
    const float* srow = g_S + (size_t)b * N_DIM;
    const float* wrow = w2 + (size_t)c * N_DIM;
    float s = 0.0f;
    for (int k = lane; k < N_DIM; k += 32) s += srow[k] * wrow[k];
    #pragma unroll
    for (int off = 16; off; off >>= 1) s += __shfl_xor_sync(0xFFFFFFFFu, s, off);
    if (lane == 0) out[(size_t)b * 10 + c] = s / 25.0f;
}

// ---------------- launch ----------------------------------------------------
extern "C" void kernel_launch(void* const* d_in, const int* in_sizes, int n_in,
                              void* d_out, int out_size) {
    const float* inp = (const float*)d_in[0];   // [8192, 784]
    const float* w1  = (const float*)d_in[1];   // [800, 784]
    const float* w2  = (const float*)d_in[2];   // [10, 800]
    float* out = (float*)d_out;                 // [8192, 10]

    k_init<<<1, 32>>>();
    k_wsplit<<<(N_PAD * K_DIM + 255) / 256, 256>>>(w1);
    k_spike_all<<<dim3(STEP_ELEMS / 16 / 256, NSTEPS), 256>>>(inp);
    k_gemm_f<<<dim3(7, 1600), 256>>>();
    k_lif_flag<<<(Z_STEP / 4 + 255) / 256, 256>>>();
    k_exact<<<WL_CAP / 256, 256>>>(w1);
    k_final<<<(B_ROWS * 10 * 32 + 255) / 256, 256>>>(w2, out);
}

// round 10
// speedup vs baseline: 2.2567x; 1.2510x over previous
#include <cuda_runtime.h>
#include <cuda_fp16.h>
#include <cstdint>

#define B_ROWS 8192
#define K_DIM  784
#define N_DIM  800
#define N_PAD  896
#define NSTEPS 25
#define STEP_ELEMS (B_ROWS * K_DIM)       // 6422528
#define M_TOTAL (NSTEPS * B_ROWS)         // 204800
#define Z_STEP  (B_ROWS * N_DIM)          // 6553600
#define WL_CAP  (1 << 20)
#define DELTA   1e-4f
#define NIT     (2 * 49)                  // 2 fp16-split passes x 49 k16 tiles

// ---------------- device scratch ------------------------------------------
__device__ __half    g_sph[(size_t)NSTEPS * STEP_ELEMS];        // sp fp16
__device__ uint32_t  g_spc[(size_t)NSTEPS * STEP_ELEMS / 16];   // 2-bit codes
__device__ float     g_Z[(size_t)NSTEPS * Z_STEP];              // fast Z
__device__ float     g_S[Z_STEP];                               // spike counts
__device__ __half    g_w1s[2][(size_t)N_PAD * K_DIM];           // w1 fp16 splits
__device__ uint2     g_keys[NSTEPS];
__device__ int       g_cnt;
__device__ int       g_wl[WL_CAP];

// ---------------- threefry2x32 (matches JAX, 20 rounds) -------------------
__device__ __forceinline__ void threefry2x32(uint32_t k0, uint32_t k1,
                                             uint32_t x0, uint32_t x1,
                                             uint32_t &o0, uint32_t &o1) {
    uint32_t ks0 = k0, ks1 = k1, ks2 = 0x1BD11BDAu ^ k0 ^ k1;
    x0 += ks0; x1 += ks1;
#define TF_R(r) { x0 += x1; x1 = __funnelshift_l(x1, x1, (r)); x1 ^= x0; }
    TF_R(13) TF_R(15) TF_R(26) TF_R(6)
    x0 += ks1; x1 += ks2 + 1u;
    TF_R(17) TF_R(29) TF_R(16) TF_R(24)
    x0 += ks2; x1 += ks0 + 2u;
    TF_R(13) TF_R(15) TF_R(26) TF_R(6)
    x0 += ks0; x1 += ks1 + 3u;
    TF_R(17) TF_R(29) TF_R(16) TF_R(24)
    x0 += ks1; x1 += ks2 + 4u;
    TF_R(13) TF_R(15) TF_R(26) TF_R(6)
    x0 += ks2; x1 += ks0 + 5u;
#undef TF_R
    o0 = x0; o1 = x1;
}

__global__ void k_init() {
    int t = threadIdx.x;
    if (t < NSTEPS) {
        uint32_t o0, o1;
        threefry2x32(0u, 42u, 0u, (uint32_t)t, o0, o1);
        g_keys[t] = make_uint2(o0, o1);
    }
    if (t == 0) g_cnt = 0;
}

// ---------------- w1 -> 2 fp16 splits (exact power-of-2 scaled) ------------
// h0 = fp16(w * 2^9), h1 = fp16((w - h0*2^-9) * 2^20).  All scales exact.
// Z = 2^-9 * (S0 + 2^-11 * S1).  Rows >= 800 zero-padded.
__global__ void k_wsplit(const float* __restrict__ w1) {
    int idx = blockIdx.x * blockDim.x + threadIdx.x;
    if (idx >= N_PAD * K_DIM) return;
    int n = idx / K_DIM;
    float w = (n < N_DIM) ? w1[idx] : 0.0f;
    __half h0 = __float2half_rn(w * 512.0f);
    float r1 = w - __half2float(h0) * 0.001953125f;          // w - h0*2^-9
    __half h1 = __float2half_rn(r1 * 1048576.0f);            // * 2^20
    g_w1s[0][idx] = h0;
    g_w1s[1][idx] = h1;
}

// ---------------- spike generation: fp16 + 2-bit codes, 16 elems/thread ----
__global__ void k_spike_all(const float* __restrict__ inp) {
    const int t = blockIdx.y;
    const uint32_t e0 = (blockIdx.x * blockDim.x + threadIdx.x) * 16u;
    if (e0 >= STEP_ELEMS) return;
    const uint2 key = g_keys[t];
    uint32_t codes = 0;
    __half sb[16];
    #pragma unroll
    for (int c = 0; c < 16; c++) {
        uint32_t o0, o1;
        threefry2x32(key.x, key.y, 0u, e0 + (uint32_t)c, o0, o1);
        uint32_t bits = o0 ^ o1;
        float r = __uint_as_float((bits >> 9) | 0x3f800000u) - 1.0f;
        float x = inp[e0 + c];
        uint32_t code = 1u;                          // sp = 0.5
        if (r * 2.0f <= fabsf(x)) {
            if (x > 0.0f)      code = 2u;            // sp = 1
            else if (x < 0.0f) code = 0u;            // sp = 0
        }
        codes |= code << (2 * c);
        unsigned short hb = code ? (unsigned short)(0x3400u + (code << 10)) : 0;
        sb[c] = __ushort_as_half(hb);                // 0 / 0.5 / 1 exact
    }
    size_t base = (size_t)t * STEP_ELEMS + e0;
    *(uint4*)(g_sph + base)     = *(uint4*)&sb[0];
    *(uint4*)(g_sph + base + 8) = *(uint4*)&sb[8];
    g_spc[base >> 4] = codes;
}

// ---------------- fast GEMM: Z = sp @ w1^T via mma.sync fp16, 2 passes -----
// Block 128M x 128N, 8 warps (2M x 4N), warp tile 64x32.
// Pass order: split1 (x2^20) then scale c by 2^-11, then split0 (x2^9);
// epilogue scales by 2^-9.  Double-buffered smem, ONE barrier per k16 tile.
__device__ __forceinline__ void ldsm_x4(uint32_t* r, uint32_t addr) {
    asm volatile("ldmatrix.sync.aligned.m8n8.x4.shared.b16 {%0,%1,%2,%3}, [%4];"
                 : "=r"(r[0]), "=r"(r[1]), "=r"(r[2]), "=r"(r[3]) : "r"(addr));
}
__device__ __forceinline__ void mma16816(float* c, const uint32_t* a,
                                         uint32_t b0, uint32_t b1) {
    asm volatile(
        "mma.sync.aligned.m16n8k16.row.col.f32.f16.f16.f32 "
        "{%0,%1,%2,%3},{%4,%5,%6,%7},{%8,%9},{%0,%1,%2,%3};"
        : "+f"(c[0]), "+f"(c[1]), "+f"(c[2]), "+f"(c[3])
        : "r"(a[0]), "r"(a[1]), "r"(a[2]), "r"(a[3]), "r"(b0), "r"(b1));
}

__global__ __launch_bounds__(256, 2) void k_gemm_f() {
    __shared__ __align__(16) char smem[2 * 2 * 128 * 48];  // [stage][A|B][row][48B]

    const int tid  = threadIdx.x;
    const int bx   = blockIdx.x;               // 0..6  (N, 128 each, pad 896)
    const int by   = blockIdx.y;               // 0..1599 (M, 128 each)
    const int warp = tid >> 5, lane = tid & 31;
    const int wm = (warp & 1) * 64;
    const int wn = (warp >> 1) * 32;

    const uint32_t sBase = (uint32_t)__cvta_generic_to_shared(smem);
    const uint32_t stageSz = 2 * 128 * 48;

    // LDSM source offsets within a stage (A at 0, B at 128*48)
    uint32_t offA[4], offB[2];
    {
        int rA = (lane & 7) + ((lane >> 3) & 1) * 8;
        int hA = lane >> 4;
        #pragma unroll
        for (int mi = 0; mi < 4; mi++)
            offA[mi] = (uint32_t)(wm + mi * 16 + rA) * 48 + hA * 16;
        int rB = (lane & 7) + ((lane >> 4) & 1) * 8;
        int hB = (lane >> 3) & 1;
        #pragma unroll
        for (int p = 0; p < 2; p++)
            offB[p] = 128 * 48 + (uint32_t)(wn + p * 16 + rB) * 48 + hB * 16;
    }

    const int rowL = tid >> 1;                 // 0..127 load row
    const int half = tid & 1;                  // 16B half of 32B row
    const __half* Abase = g_sph + (size_t)(by * 128) * K_DIM;
    const int bn = bx * 128;

    float c[4][4][4];
    #pragma unroll
    for (int mi = 0; mi < 4; mi++)
        #pragma unroll
        for (int ni = 0; ni < 4; ni++)
            #pragma unroll
            for (int q = 0; q < 4; q++) c[mi][ni][q] = 0.0f;

    // prologue: tile 0 = split 1, kt 0
    uint4 av = *(const uint4*)(Abase + (size_t)rowL * K_DIM + half * 8);
    uint4 bv = *(const uint4*)(g_w1s[1] + (size_t)(bn + rowL) * K_DIM + half * 8);
    *(uint4*)(smem + rowL * 48 + half * 16)            = av;
    *(uint4*)(smem + 128 * 48 + rowL * 48 + half * 16) = bv;
    __syncthreads();

    #pragma unroll 1
    for (int it = 0; it < NIT; it++) {
        const uint32_t sCur = sBase + (uint32_t)(it & 1) * stageSz;

        // prefetch tile it+1 into registers
        if (it + 1 < NIT) {
            int it2 = it + 1;
            int s2  = (it2 < 49) ? 1 : 0;
            int kt2 = (it2 < 49) ? it2 : it2 - 49;
            av = *(const uint4*)(Abase + (size_t)rowL * K_DIM + kt2 * 16 + half * 8);
            bv = *(const uint4*)(g_w1s[s2] + (size_t)(bn + rowL) * K_DIM + kt2 * 16 + half * 8);
        }

        // compute on current stage
        uint32_t a[4][4], bf[2][4];
        #pragma unroll
        for (int mi = 0; mi < 4; mi++) ldsm_x4(a[mi], sCur + offA[mi]);
        #pragma unroll
        for (int p = 0; p < 2; p++)    ldsm_x4(bf[p], sCur + offB[p]);
        #pragma unroll
        for (int mi = 0; mi < 4; mi++)
            #pragma unroll
            for (int ni = 0; ni < 4; ni++)
                mma16816(c[mi][ni], a[mi], bf[ni >> 1][(ni & 1) * 2],
                         bf[ni >> 1][(ni & 1) * 2 + 1]);

        // end of split-1 pass: scale by 2^-11 (exact)
        if (it == 48) {
            #pragma unroll
            for (int mi = 0; mi < 4; mi++)
                #pragma unroll
                for (int ni = 0; ni < 4; ni++)
                    #pragma unroll
                    for (int q = 0; q < 4; q++)
                        c[mi][ni][q] *= 4.8828125e-4f;
        }

        // store next tile into the other stage; one barrier per tile
        if (it + 1 < NIT) {
            char* dst = smem + ((it + 1) & 1) * stageSz;
            *(uint4*)(dst + rowL * 48 + half * 16)            = av;
            *(uint4*)(dst + 128 * 48 + rowL * 48 + half * 16) = bv;
            __syncthreads();
        }
    }

    // store Z = 2^-9 * csum (guard padded cols)
    const int r0 = by * 128 + wm + (lane >> 2);
    const int c0 = bn + wn + (lane & 3) * 2;
    #pragma unroll
    for (int mi = 0; mi < 4; mi++)
        #pragma unroll
        for (int ni = 0; ni < 4; ni++) {
            int col = c0 + ni * 8;
            if (col < N_DIM) {
                int row = r0 + mi * 16;
                *(float2*)(g_Z + (size_t)row * N_DIM + col) =
                    make_float2(c[mi][ni][0] * 0.001953125f,
                                c[mi][ni][1] * 0.001953125f);
                *(float2*)(g_Z + (size_t)(row + 8) * N_DIM + col) =
                    make_float2(c[mi][ni][2] * 0.001953125f,
                                c[mi][ni][3] * 0.001953125f);
            }
        }
}

// ---------------- LIF + flagging (16 elems/thread, MLP-4 + prefetch) --------
__global__ void k_lif_flag() {
    const int q = blockIdx.x * blockDim.x + threadIdx.x;
    if (q >= Z_STEP / 16) return;
    const int idx = q * 16;
    const float cL = 0.95f;
    const float cI = 0.05000000074505806f;
    float m[16], cnt[16];
    unsigned flag = 0;
    #pragma unroll
    for (int h = 0; h < 16; h++) { m[h] = 0.0f; cnt[h] = 0.0f; }

    float4 z[4];
    #pragma unroll
    for (int v = 0; v < 4; v++)
        z[v] = *(const float4*)(g_Z + idx + v * 4);

    #pragma unroll 1
    for (int t = 0; t < NSTEPS; t++) {
        float4 zn[4];
        if (t + 1 < NSTEPS) {
            #pragma unroll
            for (int v = 0; v < 4; v++)
                zn[v] = *(const float4*)(g_Z + (size_t)(t + 1) * Z_STEP + idx + v * 4);
        }
        #pragma unroll
        for (int v = 0; v < 4; v++) {
            const float* zp = &z[v].x;
            #pragma unroll
            for (int u = 0; u < 4; u++) {
                int h = v * 4 + u;
                m[h] = __fadd_rn(__fmul_rn(cL, m[h]), __fmul_rn(cI, zp[u]));
                float thr = __fadd_rn(m[h], -1.0f);
                if (fabsf(thr) <= DELTA) flag |= 1u << h;
                if (thr > 0.0f) { cnt[h] += 1.0f; m[h] = __fadd_rn(m[h], -1.0f); }
            }
        }
        if (t + 1 < NSTEPS) {
            #pragma unroll
            for (int v = 0; v < 4; v++) z[v] = zn[v];
        }
    }
    #pragma unroll
    for (int v = 0; v < 4; v++)
        *(float4*)(g_S + idx + v * 4) =
            make_float4(cnt[v*4], cnt[v*4+1], cnt[v*4+2], cnt[v*4+3]);
    while (flag) {
        int h = __ffs(flag) - 1;
        flag &= flag - 1;
        int p = atomicAdd(&g_cnt, 1);
        if (p < WL_CAP) g_wl[p] = idx + h;
    }
}

// ---------------- exact recompute of flagged elements -----------------------
// Eigen kc=248 panel chains from 2-bit codes (validated fp32 ordering).
__global__ void k_exact(const float* __restrict__ w1) {
    const int i = blockIdx.x * blockDim.x + threadIdx.x;
    int n = g_cnt; if (n > WL_CAP) n = WL_CAP;
    if (i >= n) return;
    const int e = g_wl[i];
    const int b = e / N_DIM, j = e % N_DIM;
    const float* wrow = w1 + (size_t)j * K_DIM;
    const int pend[4] = {248, 496, 744, 784};
    const float cL = 0.95f;
    const float cI = 0.05000000074505806f;
    float m = 0.0f, cnt = 0.0f;
    #pragma unroll 1
    for (int t = 0; t < NSTEPS; t++) {
        const uint32_t* cw = g_spc + (((size_t)t * STEP_ELEMS + (size_t)b * K_DIM) >> 4);
        float csum = 0.0f;
        int k = 0;
        #pragma unroll 1
        for (int p = 0; p < 4; p++) {
            float acc = 0.0f;
            #pragma unroll 4
            for (; k < pend[p]; k++) {
                uint32_t code = (cw[k >> 4] >> ((k & 15) * 2)) & 3u;
                float sp = 0.5f * (float)code;
                acc = __fmaf_rn(sp, wrow[k], acc);
            }
            csum = __fadd_rn(csum, acc);
        }
        m = __fadd_rn(__fmul_rn(cL, m), __fmul_rn(cI, csum));
        float thr = __fadd_rn(m, -1.0f);
        if (thr > 0.0f) { cnt += 1.0f; m = __fadd_rn(m, -1.0f); }
    }
    g_S[e] = cnt;
}

// ---------------- final: out = (S @ w2^T) / 25 ------------------------------
__global__ void k_final(const float* __restrict__ w2, float* __restrict__ out) {
    int gw   = (blockIdx.x * blockDim.x + threadIdx.x) >> 5;
    int lane = threadIdx.x & 31;
    if (gw >= B_ROWS * 10) return;
    int b = gw / 10, c = gw % 10;
    const float* srow = g_S + (size_t)b * N_DIM;
    const float* wrow = w2 + (size_t)c * N_DIM;
    float s = 0.0f;
    for (int k = lane; k < N_DIM; k += 32) s += srow[k] * wrow[k];
    #pragma unroll
    for (int off = 16; off; off >>= 1) s += __shfl_xor_sync(0xFFFFFFFFu, s, off);
    if (lane == 0) out[(size_t)b * 10 + c] = s / 25.0f;
}

// ---------------- launch ----------------------------------------------------
extern "C" void kernel_launch(void* const* d_in, const int* in_sizes, int n_in,
                              void* d_out, int out_size) {
    const float* inp = (const float*)d_in[0];   // [8192, 784]
    const float* w1  = (const float*)d_in[1];   // [800, 784]
    const float* w2  = (const float*)d_in[2];   // [10, 800]
    float* out = (float*)d_out;                 // [8192, 10]

    k_init<<<1, 32>>>();
    k_wsplit<<<(N_PAD * K_DIM + 255) / 256, 256>>>(w1);
    k_spike_all<<<dim3(STEP_ELEMS / 16 / 256, NSTEPS), 256>>>(inp);
    k_gemm_f<<<dim3(7, 1600), 256>>>();
    k_lif_flag<<<(Z_STEP / 16 + 255) / 256, 256>>>();
    k_exact<<<WL_CAP / 256, 256>>>(w1);
    k_final<<<(B_ROWS * 10 * 32 + 255) / 256, 256>>>(w2, out);
}